// round 1
// baseline (speedup 1.0000x reference)
#include <cuda_runtime.h>
#include <cstdint>

// ---------------------------------------------------------------------------
// Problem dims
//   B=64, N=512 -> R = 32768 token rows, D = 1024, M = 256 objects
// ---------------------------------------------------------------------------
#define R_TOK   32768
#define DIM     1024
#define M_OBJ   256

// ---------------------------------------------------------------------------
// Scratch (no cudaMalloc allowed -> __device__ globals)
// ---------------------------------------------------------------------------
__device__ float g_oln [M_OBJ * DIM];          // LN(object_vector)
__device__ float g_kT  [DIM * M_OBJ];          // k transposed [D, M]
__device__ float g_v   [M_OBJ * DIM];          // v
__device__ float g_pln [R_TOK * DIM];          // LN(p)  (later reused as p2)
__device__ float g_q   [R_TOK * DIM];          // q      (later reused as G2)
__device__ float g_att [R_TOK * M_OBJ];        // logits -> softmax A
__device__ float g_p1  [R_TOK * DIM];          // p after attention residual
__device__ float g_G1  [R_TOK * DIM];          // W1 out -> h1
__device__ float g_invn[64 * 256];             // BCIM inverse norms

// ---------------------------------------------------------------------------
// tf32 GEMM: C[M,N] = A[M,K] @ B[K,N] (+epilogue)
//   EPI 0: +bias        EPI 1: +resid (no bias)
//   EPI 2: plain        EPI 3: +bias, store transposed C[n*M + m]
//   SPLIT: 2-term tf32 error compensation (3 MMAs)
// Tiles: BM=128, BN=128, BK=32; 256 threads (8 warps, 4x2 warp grid)
// ---------------------------------------------------------------------------
#define BM 128
#define BN 128
#define BK 32
#define AP (BK + 4)     // As pad: stride 36 words -> conflict-free frag loads
#define BP (BN + 8)     // Bs pad: stride 136 words -> conflict-free frag loads
#define GEMM_SMEM_FLOATS (2 * BM * AP + 2 * BK * BP)

__device__ __forceinline__ uint32_t cvt_tf32(float x) {
    uint32_t r;
    asm("cvt.rna.tf32.f32 %0, %1;" : "=r"(r) : "f"(x));
    return r;
}

__device__ __forceinline__ void mma8(float (&d)[4], const uint32_t (&a)[4],
                                     const uint32_t (&b)[2]) {
    asm volatile(
        "mma.sync.aligned.m16n8k8.row.col.f32.tf32.tf32.f32 "
        "{%0,%1,%2,%3},{%4,%5,%6,%7},{%8,%9},{%0,%1,%2,%3};"
        : "+f"(d[0]), "+f"(d[1]), "+f"(d[2]), "+f"(d[3])
        : "r"(a[0]), "r"(a[1]), "r"(a[2]), "r"(a[3]), "r"(b[0]), "r"(b[1]));
}

__device__ __forceinline__ void cpa16(float* s, const float* g) {
    uint32_t sa = (uint32_t)__cvta_generic_to_shared(s);
    asm volatile("cp.async.cg.shared.global [%0], [%1], 16;" :: "r"(sa), "l"(g));
}

template <int EPI, bool SPLIT>
__global__ void __launch_bounds__(256)
gemm_kernel(const float* __restrict__ A, const float* __restrict__ B,
            const float* __restrict__ bias, const float* __restrict__ resid,
            float* __restrict__ C, int M, int N, int K)
{
    extern __shared__ float sm[];
    float* As = sm;                  // [2][BM][AP]
    float* Bs = sm + 2 * BM * AP;    // [2][BK][BP]

    const int tid  = threadIdx.x;
    const int lane = tid & 31;
    const int warp = tid >> 5;
    const int wm = warp >> 1;        // 0..3  (32 rows each)
    const int wn = warp & 1;         // 0..1  (64 cols each)
    const int row0 = blockIdx.y * BM;
    const int col0 = blockIdx.x * BN;

    float acc[2][8][4];
#pragma unroll
    for (int i = 0; i < 2; i++)
#pragma unroll
        for (int j = 0; j < 8; j++)
#pragma unroll
            for (int l = 0; l < 4; l++) acc[i][j][l] = 0.f;

    const int arow = tid >> 3, acol = (tid & 7) * 4;
    const int brow = tid >> 5, bcol = (tid & 31) * 4;

    const int nk = K / BK;

    // ---- prologue: load stage 0 ----
    {
        const float* Ag = A + (size_t)row0 * K;
        const float* Bg = B + col0;
#pragma unroll
        for (int i = 0; i < 4; i++) {
            int r = arow + i * 32;
            cpa16(As + r * AP + acol, Ag + (size_t)r * K + acol);
        }
#pragma unroll
        for (int i = 0; i < 4; i++) {
            int r = brow + i * 8;
            cpa16(Bs + r * BP + bcol, Bg + (size_t)r * N + bcol);
        }
        asm volatile("cp.async.commit_group;");
    }

    for (int kt = 0; kt < nk; kt++) {
        int s = kt & 1;
        if (kt + 1 < nk) {
            // issue next stage loads
            int s2 = s ^ 1;
            const float* Ag = A + (size_t)row0 * K + (size_t)(kt + 1) * BK;
            const float* Bg = B + (size_t)((kt + 1) * BK) * N + col0;
            float* Ads = As + s2 * BM * AP;
            float* Bds = Bs + s2 * BK * BP;
#pragma unroll
            for (int i = 0; i < 4; i++) {
                int r = arow + i * 32;
                cpa16(Ads + r * AP + acol, Ag + (size_t)r * K + acol);
            }
#pragma unroll
            for (int i = 0; i < 4; i++) {
                int r = brow + i * 8;
                cpa16(Bds + r * BP + bcol, Bg + (size_t)r * N + bcol);
            }
            asm volatile("cp.async.commit_group;");
            asm volatile("cp.async.wait_group 1;");
        } else {
            asm volatile("cp.async.wait_group 0;");
        }
        __syncthreads();

        const float* Asl = As + s * BM * AP;
        const float* Bsl = Bs + s * BK * BP;

#pragma unroll
        for (int kk = 0; kk < BK; kk += 8) {
            uint32_t ah[2][4], al[2][4];
#pragma unroll
            for (int mt = 0; mt < 2; mt++) {
                int rb = wm * 32 + mt * 16 + (lane >> 2);
                int cc = kk + (lane & 3);
                float x0 = Asl[rb * AP + cc];
                float x1 = Asl[(rb + 8) * AP + cc];
                float x2 = Asl[rb * AP + cc + 4];
                float x3 = Asl[(rb + 8) * AP + cc + 4];
                ah[mt][0] = cvt_tf32(x0);
                ah[mt][1] = cvt_tf32(x1);
                ah[mt][2] = cvt_tf32(x2);
                ah[mt][3] = cvt_tf32(x3);
                if (SPLIT) {
                    al[mt][0] = cvt_tf32(x0 - __uint_as_float(ah[mt][0]));
                    al[mt][1] = cvt_tf32(x1 - __uint_as_float(ah[mt][1]));
                    al[mt][2] = cvt_tf32(x2 - __uint_as_float(ah[mt][2]));
                    al[mt][3] = cvt_tf32(x3 - __uint_as_float(ah[mt][3]));
                }
            }
#pragma unroll
            for (int nt = 0; nt < 8; nt++) {
                int cb = wn * 64 + nt * 8 + (lane >> 2);
                int r0 = kk + (lane & 3);
                float y0 = Bsl[r0 * BP + cb];
                float y1 = Bsl[(r0 + 4) * BP + cb];
                uint32_t bh[2] = {cvt_tf32(y0), cvt_tf32(y1)};
                if (SPLIT) {
                    uint32_t bl[2] = {cvt_tf32(y0 - __uint_as_float(bh[0])),
                                      cvt_tf32(y1 - __uint_as_float(bh[1]))};
#pragma unroll
                    for (int mt = 0; mt < 2; mt++) {
                        mma8(acc[mt][nt], ah[mt], bh);
                        mma8(acc[mt][nt], al[mt], bh);
                        mma8(acc[mt][nt], ah[mt], bl);
                    }
                } else {
                    mma8(acc[0][nt], ah[0], bh);
                    mma8(acc[1][nt], ah[1], bh);
                }
            }
        }
        __syncthreads();
    }

    // ---- epilogue ----
#pragma unroll
    for (int mt = 0; mt < 2; mt++) {
        int gr = row0 + wm * 32 + mt * 16 + (lane >> 2);
#pragma unroll
        for (int nt = 0; nt < 8; nt++) {
            int gc = col0 + wn * 64 + nt * 8 + (lane & 3) * 2;
            float v00 = acc[mt][nt][0], v01 = acc[mt][nt][1];
            float v10 = acc[mt][nt][2], v11 = acc[mt][nt][3];
            if (EPI == 0 || EPI == 3) {
                float b0 = bias[gc], b1 = bias[gc + 1];
                v00 += b0; v01 += b1; v10 += b0; v11 += b1;
            }
            if (EPI == 1) {
                v00 += resid[(size_t)gr * N + gc];
                v01 += resid[(size_t)gr * N + gc + 1];
                v10 += resid[(size_t)(gr + 8) * N + gc];
                v11 += resid[(size_t)(gr + 8) * N + gc + 1];
            }
            if (EPI == 3) {
                C[(size_t)gc * M + gr]           = v00;
                C[(size_t)(gc + 1) * M + gr]     = v01;
                C[(size_t)gc * M + gr + 8]       = v10;
                C[(size_t)(gc + 1) * M + gr + 8] = v11;
            } else {
                *(float2*)(C + (size_t)gr * N + gc)       = make_float2(v00, v01);
                *(float2*)(C + (size_t)(gr + 8) * N + gc) = make_float2(v10, v11);
            }
        }
    }
}

// ---------------------------------------------------------------------------
// Block reduction of two values (256 threads)
// ---------------------------------------------------------------------------
__device__ __forceinline__ void blockReduce2(float& a, float& b) {
    __shared__ float sa[8], sb[8];
#pragma unroll
    for (int o = 16; o; o >>= 1) {
        a += __shfl_xor_sync(0xffffffffu, a, o);
        b += __shfl_xor_sync(0xffffffffu, b, o);
    }
    int w = threadIdx.x >> 5, l = threadIdx.x & 31;
    if (l == 0) { sa[w] = a; sb[w] = b; }
    __syncthreads();
    float ta = 0.f, tb = 0.f;
#pragma unroll
    for (int i = 0; i < 8; i++) { ta += sa[i]; tb += sb[i]; }
    a = ta; b = tb;
}

// ---------------------------------------------------------------------------
// Row LayerNorm over D=1024 (one block of 256 threads per row)
// ---------------------------------------------------------------------------
__global__ void ln_kernel(const float* __restrict__ x, const float* __restrict__ g,
                          const float* __restrict__ b, float* __restrict__ y)
{
    size_t base = (size_t)blockIdx.x * DIM;
    int t = threadIdx.x;
    float4 v = *(const float4*)(x + base + t * 4);
    float s  = v.x + v.y + v.z + v.w;
    float ss = v.x * v.x + v.y * v.y + v.z * v.z + v.w * v.w;
    blockReduce2(s, ss);
    float mu  = s * (1.f / DIM);
    float var = ss * (1.f / DIM) - mu * mu;
    float inv = rsqrtf(var + 1e-5f);
    float4 gg = *(const float4*)(g + t * 4);
    float4 bb = *(const float4*)(b + t * 4);
    float4 o;
    o.x = (v.x - mu) * inv * gg.x + bb.x;
    o.y = (v.y - mu) * inv * gg.y + bb.y;
    o.z = (v.z - mu) * inv * gg.z + bb.z;
    o.w = (v.w - mu) * inv * gg.w + bb.w;
    *(float4*)(y + base + t * 4) = o;
}

// ---------------------------------------------------------------------------
// LN -> exact GELU (-> +resid) over D=1024 rows
// ---------------------------------------------------------------------------
__device__ __forceinline__ float gelu_exact(float x) {
    return 0.5f * x * (1.f + erff(x * 0.70710678118654752f));
}

template <bool RESID>
__global__ void ln_gelu_kernel(const float* __restrict__ x, const float* __restrict__ g,
                               const float* __restrict__ b, const float* __restrict__ resid,
                               float* __restrict__ y)
{
    size_t base = (size_t)blockIdx.x * DIM;
    int t = threadIdx.x;
    float4 v = *(const float4*)(x + base + t * 4);
    float s  = v.x + v.y + v.z + v.w;
    float ss = v.x * v.x + v.y * v.y + v.z * v.z + v.w * v.w;
    blockReduce2(s, ss);
    float mu  = s * (1.f / DIM);
    float var = ss * (1.f / DIM) - mu * mu;
    float inv = rsqrtf(var + 1e-5f);
    float4 gg = *(const float4*)(g + t * 4);
    float4 bb = *(const float4*)(b + t * 4);
    float4 o;
    o.x = gelu_exact((v.x - mu) * inv * gg.x + bb.x);
    o.y = gelu_exact((v.y - mu) * inv * gg.y + bb.y);
    o.z = gelu_exact((v.z - mu) * inv * gg.z + bb.z);
    o.w = gelu_exact((v.w - mu) * inv * gg.w + bb.w);
    if (RESID) {
        float4 r = *(const float4*)(resid + base + t * 4);
        o.x += r.x; o.y += r.y; o.z += r.z; o.w += r.w;
    }
    *(float4*)(y + base + t * 4) = o;
}

// ---------------------------------------------------------------------------
// Softmax over rows of 256 (one warp per row, 8 rows per block)
// ---------------------------------------------------------------------------
__global__ void softmax_kernel(float* __restrict__ a)
{
    int row = blockIdx.x * 8 + (threadIdx.x >> 5);
    int l = threadIdx.x & 31;
    float* p = a + (size_t)row * M_OBJ;
    float4 v0 = ((float4*)p)[l];
    float4 v1 = ((float4*)p)[l + 32];
    float m = fmaxf(fmaxf(fmaxf(v0.x, v0.y), fmaxf(v0.z, v0.w)),
                    fmaxf(fmaxf(v1.x, v1.y), fmaxf(v1.z, v1.w)));
#pragma unroll
    for (int o = 16; o; o >>= 1) m = fmaxf(m, __shfl_xor_sync(0xffffffffu, m, o));
    v0.x = __expf(v0.x - m); v0.y = __expf(v0.y - m);
    v0.z = __expf(v0.z - m); v0.w = __expf(v0.w - m);
    v1.x = __expf(v1.x - m); v1.y = __expf(v1.y - m);
    v1.z = __expf(v1.z - m); v1.w = __expf(v1.w - m);
    float s = v0.x + v0.y + v0.z + v0.w + v1.x + v1.y + v1.z + v1.w;
#pragma unroll
    for (int o = 16; o; o >>= 1) s += __shfl_xor_sync(0xffffffffu, s, o);
    float inv = 1.f / s;
    v0.x *= inv; v0.y *= inv; v0.z *= inv; v0.w *= inv;
    v1.x *= inv; v1.y *= inv; v1.z *= inv; v1.w *= inv;
    ((float4*)p)[l] = v0;
    ((float4*)p)[l + 32] = v1;
}

// ---------------------------------------------------------------------------
// BCIM part 1: inverse norms of 2048-dim concat vectors per (b, hw)
//   vec(b,hw) = concat(p2[b,hw,:], p2[b,hw+256,:])
// ---------------------------------------------------------------------------
__global__ void bcim_norm_kernel(const float* __restrict__ p, float* __restrict__ invn)
{
    int bid = blockIdx.x;                 // b*256 + hw
    int b = bid >> 8, hw = bid & 255;
    size_t r0 = ((size_t)b * 512 + hw) * DIM;
    size_t r1 = r0 + (size_t)256 * DIM;
    int t = threadIdx.x;
    float4 a = *(const float4*)(p + r0 + t * 4);
    float4 c = *(const float4*)(p + r1 + t * 4);
    float ss = a.x * a.x + a.y * a.y + a.z * a.z + a.w * a.w +
               c.x * c.x + c.y * c.y + c.z * c.z + c.w * c.w;
    float dummy = 0.f;
    blockReduce2(ss, dummy);
    if (t == 0) invn[bid] = rsqrtf(ss);
}

// ---------------------------------------------------------------------------
// BCIM part 2: sim[b,hw] = (1 + sum_{valid nbrs} <u,u'> ) / 9 ; scale + write out
// ---------------------------------------------------------------------------
__global__ void bcim_sim_kernel(const float* __restrict__ p, const float* __restrict__ invn,
                                float* __restrict__ out)
{
    int bid = blockIdx.x;
    int b = bid >> 8, hw = bid & 255;
    int h = hw >> 4, w = hw & 15;
    size_t base = (size_t)b * 512 * DIM;
    int t = threadIdx.x;

    float own[8];
#pragma unroll
    for (int j = 0; j < 8; j++) {
        int e = t + j * 256;
        int row = hw + ((e >> 10) << 8);
        own[j] = p[base + (size_t)row * DIM + (e & 1023)];
    }

    const int DH[8] = {-1, -1, -1, 0, 0, 1, 1, 1};
    const int DW[8] = {-1, 0, 1, -1, 1, -1, 0, 1};
    float dacc[8];
#pragma unroll
    for (int nb = 0; nb < 8; nb++) {
        dacc[nb] = 0.f;
        int h2 = h + DH[nb], w2 = w + DW[nb];
        if ((unsigned)h2 < 16u && (unsigned)w2 < 16u) {
            int hw2 = h2 * 16 + w2;
#pragma unroll
            for (int j = 0; j < 8; j++) {
                int e = t + j * 256;
                int row = hw2 + ((e >> 10) << 8);
                dacc[nb] += own[j] * p[base + (size_t)row * DIM + (e & 1023)];
            }
        }
    }
#pragma unroll
    for (int nb = 0; nb < 8; nb++)
#pragma unroll
        for (int o = 16; o; o >>= 1) dacc[nb] += __shfl_xor_sync(0xffffffffu, dacc[nb], o);

    __shared__ float part[8][8];
    __shared__ float s_sim;
    int wp = t >> 5, l = t & 31;
    if (l == 0) {
#pragma unroll
        for (int nb = 0; nb < 8; nb++) part[wp][nb] = dacc[nb];
    }
    __syncthreads();
    if (t == 0) {
        float inv0 = invn[bid];
        float sim = 1.f;  // self term: <u,u> = 1
#pragma unroll
        for (int nb = 0; nb < 8; nb++) {
            int h2 = h + DH[nb], w2 = w + DW[nb];
            if ((unsigned)h2 < 16u && (unsigned)w2 < 16u) {
                float d = 0.f;
                for (int k = 0; k < 8; k++) d += part[k][nb];
                sim += d * inv0 * invn[(b << 8) + h2 * 16 + w2];
            }
        }
        s_sim = sim * (1.f / 9.f);
    }
    __syncthreads();
    float sim = s_sim;
#pragma unroll
    for (int j = 0; j < 8; j++) {
        int e = t + j * 256;
        int row = hw + ((e >> 10) << 8);
        out[base + (size_t)row * DIM + (e & 1023)] = own[j] * sim;
    }
}

// ---------------------------------------------------------------------------
// Launch
// ---------------------------------------------------------------------------
extern "C" void kernel_launch(void* const* d_in, const int* in_sizes, int n_in,
                              void* d_out, int out_size)
{
    const float* p_vec = (const float*)d_in[0];
    const float* obj   = (const float*)d_in[1];
    const float* lnpg  = (const float*)d_in[2];
    const float* lnpb  = (const float*)d_in[3];
    const float* lnog  = (const float*)d_in[4];
    const float* lnob  = (const float*)d_in[5];
    const float* Wq = (const float*)d_in[6],  *bq = (const float*)d_in[7];
    const float* Wk = (const float*)d_in[8],  *bk = (const float*)d_in[9];
    const float* Wv = (const float*)d_in[10], *bv = (const float*)d_in[11];
    const float* W1 = (const float*)d_in[12], *b1 = (const float*)d_in[13];
    const float* l1g = (const float*)d_in[14], *l1b = (const float*)d_in[15];
    const float* W2 = (const float*)d_in[16], *b2 = (const float*)d_in[17];
    const float* l2g = (const float*)d_in[18], *l2b = (const float*)d_in[19];
    float* out = (float*)d_out;

    float *oln, *kT, *vb, *pln, *q, *att, *p1, *G1, *invn;
    cudaGetSymbolAddress((void**)&oln,  g_oln);
    cudaGetSymbolAddress((void**)&kT,   g_kT);
    cudaGetSymbolAddress((void**)&vb,   g_v);
    cudaGetSymbolAddress((void**)&pln,  g_pln);
    cudaGetSymbolAddress((void**)&q,    g_q);
    cudaGetSymbolAddress((void**)&att,  g_att);
    cudaGetSymbolAddress((void**)&p1,   g_p1);
    cudaGetSymbolAddress((void**)&G1,   g_G1);
    cudaGetSymbolAddress((void**)&invn, g_invn);

    const int SMEM = GEMM_SMEM_FLOATS * sizeof(float);  // 71680 B
    cudaFuncSetAttribute(gemm_kernel<0, false>, cudaFuncAttributeMaxDynamicSharedMemorySize, SMEM);
    cudaFuncSetAttribute(gemm_kernel<1, false>, cudaFuncAttributeMaxDynamicSharedMemorySize, SMEM);
    cudaFuncSetAttribute(gemm_kernel<0, true >, cudaFuncAttributeMaxDynamicSharedMemorySize, SMEM);
    cudaFuncSetAttribute(gemm_kernel<2, true >, cudaFuncAttributeMaxDynamicSharedMemorySize, SMEM);
    cudaFuncSetAttribute(gemm_kernel<3, true >, cudaFuncAttributeMaxDynamicSharedMemorySize, SMEM);

    // 1) LN(object), LN(p)
    ln_kernel<<<M_OBJ, 256>>>(obj, lnog, lnob, oln);
    ln_kernel<<<R_TOK, 256>>>(p_vec, lnpg, lnpb, pln);

    // 2) k^T = (o_ln @ Wk + bk)^T   (split tf32: feeds peaked softmax)
    gemm_kernel<3, true><<<dim3(DIM / BN, M_OBJ / BM), 256, SMEM>>>(
        oln, Wk, bk, nullptr, kT, M_OBJ, DIM, DIM);
    // 3) v = o_ln @ Wv + bv
    gemm_kernel<0, false><<<dim3(DIM / BN, M_OBJ / BM), 256, SMEM>>>(
        oln, Wv, bv, nullptr, vb, M_OBJ, DIM, DIM);
    // 4) q = p_ln @ Wq + bq  (split tf32)
    gemm_kernel<0, true><<<dim3(DIM / BN, R_TOK / BM), 256, SMEM>>>(
        pln, Wq, bq, nullptr, q, R_TOK, DIM, DIM);
    // 5) logits = q @ k^T  (split tf32)
    gemm_kernel<2, true><<<dim3(M_OBJ / BN, R_TOK / BM), 256, SMEM>>>(
        q, kT, nullptr, nullptr, att, R_TOK, M_OBJ, DIM);
    // 6) softmax rows
    softmax_kernel<<<R_TOK / 8, 256>>>(att);
    // 7) p1 = p_ln + A @ v
    gemm_kernel<1, false><<<dim3(DIM / BN, R_TOK / BM), 256, SMEM>>>(
        att, vb, nullptr, pln, p1, R_TOK, DIM, M_OBJ);
    // 8) G1 = p1 @ W1 + b1 ; h1 = gelu(LN(G1)) in place
    gemm_kernel<0, false><<<dim3(DIM / BN, R_TOK / BM), 256, SMEM>>>(
        p1, W1, b1, nullptr, G1, R_TOK, DIM, DIM);
    ln_gelu_kernel<false><<<R_TOK, 256>>>(G1, l1g, l1b, nullptr, G1);
    // 9) G2 = h1 @ W2 + b2 (reuse q buffer) ; p2 = p1 + gelu(LN(G2)) -> pln buffer
    gemm_kernel<0, false><<<dim3(DIM / BN, R_TOK / BM), 256, SMEM>>>(
        G1, W2, b2, nullptr, q, R_TOK, DIM, DIM);
    ln_gelu_kernel<true><<<R_TOK, 256>>>(q, l2g, l2b, p1, pln);
    // 10) BCIM
    bcim_norm_kernel<<<64 * 256, 256>>>(pln, invn);
    bcim_sim_kernel<<<64 * 256, 256>>>(pln, invn, out);
}

// round 3
// speedup vs baseline: 1.4772x; 1.4772x over previous
#include <cuda_runtime.h>
#include <cstdint>

// ---------------------------------------------------------------------------
// Dims: B=64, N=512 -> R = 32768 rows, D = 1024, M = 256 objects
// ---------------------------------------------------------------------------
#define R_TOK   32768
#define DIM     1024
#define M_OBJ   256
#define K3      3072          // 3*DIM split-embedded contraction

// ---------------------------------------------------------------------------
// Scratch (__device__ globals; no cudaMalloc allowed)
// ---------------------------------------------------------------------------
__device__ float g_oln3 [M_OBJ * K3];          // LN(o) as A-side 3K [hi|lo|hi]
__device__ float g_Wk3  [K3 * DIM];            // Wk as B-side 3K [hi;hi;lo]
__device__ float g_Wq3  [DIM * K3];            // Wq as A-side 3K
__device__ float g_Wvr  [DIM * DIM];           // tf32-rounded Wv
__device__ float g_W1r  [DIM * DIM];
__device__ float g_W2r  [DIM * DIM];
__device__ float g_kT3  [K3 * M_OBJ];          // k^T as B-side 3K (bias added)
__device__ float g_Wqk3 [K3 * M_OBJ];          // (Wq@k^T) as B-side 3K
__device__ float g_bias [M_OBJ];               // bq . k[m]
__device__ float g_pln3 [(size_t)R_TOK * K3];  // LN(p) A-side 3K; later: G2, p2
__device__ float g_att  [(size_t)R_TOK * M_OBJ];
__device__ float g_p1   [(size_t)R_TOK * DIM];
__device__ float g_G1   [(size_t)R_TOK * DIM];
__device__ float g_invn [64 * 256];

// ---------------------------------------------------------------------------
// Helpers
// ---------------------------------------------------------------------------
__device__ __forceinline__ float round_tf32(float x) {
    uint32_t u;
    asm("cvt.rna.tf32.f32 %0, %1;" : "=r"(u) : "f"(x));
    return __uint_as_float(u);
}

__device__ __forceinline__ void mma8(float (&d)[4], const uint32_t (&a)[4],
                                     const uint32_t (&b)[2]) {
    asm volatile(
        "mma.sync.aligned.m16n8k8.row.col.f32.tf32.tf32.f32 "
        "{%0,%1,%2,%3},{%4,%5,%6,%7},{%8,%9},{%0,%1,%2,%3};"
        : "+f"(d[0]), "+f"(d[1]), "+f"(d[2]), "+f"(d[3])
        : "r"(a[0]), "r"(a[1]), "r"(a[2]), "r"(a[3]), "r"(b[0]), "r"(b[1]));
}

__device__ __forceinline__ void cpa16(float* s, const float* g) {
    uint32_t sa = (uint32_t)__cvta_generic_to_shared(s);
    asm volatile("cp.async.cg.shared.global [%0], [%1], 16;" :: "r"(sa), "l"(g));
}

// ---------------------------------------------------------------------------
// cvt-free tf32 GEMM, 3-stage cp.async pipeline
// Tiles: BM=128, BN=128, BK=32; 256 threads (8 warps; warp tile 32x64)
// EPI 0: +bias(col), plain store
// EPI 1: +bias(col), tf32-rounded store
// EPI 2: +resid (pln3 hi+lo, stride rstride), tf32-rounded store
// EPI 3: +bias(col), transposed split-3K store to C[3K][ldc]  (k-GEMM)
// EPI 4: split-3K row store to C[3K][ldc]                     (Wqk-GEMM)
// ---------------------------------------------------------------------------
#define BM 128
#define BN 128
#define BK 32
#define AP (BK + 4)
#define BP (BN + 8)
#define STAGES 3
#define GEMM_SMEM_BYTES (STAGES * (BM * AP + BK * BP) * 4)   // 107520

template <int EPI>
__global__ void __launch_bounds__(256)
gemm3(const float* __restrict__ A, const float* __restrict__ B,
      const float* __restrict__ bias, const float* __restrict__ resid,
      float* __restrict__ C, int Mm, int Nn, int Kk,
      int lda, int ldb, int ldc, int rstride)
{
    extern __shared__ float sm[];
    float* As = sm;
    float* Bs = sm + STAGES * BM * AP;

    const int tid  = threadIdx.x;
    const int lane = tid & 31;
    const int warp = tid >> 5;
    const int wm = warp >> 1;
    const int wn = warp & 1;
    const int row0 = blockIdx.y * BM;
    const int col0 = blockIdx.x * BN;

    float acc[2][8][4];
#pragma unroll
    for (int i = 0; i < 2; i++)
#pragma unroll
        for (int j = 0; j < 8; j++)
#pragma unroll
            for (int l = 0; l < 4; l++) acc[i][j][l] = 0.f;

    const int arow = tid >> 3, acol = (tid & 7) * 4;
    const int brow = tid >> 5, bcol = (tid & 31) * 4;
    const int nk = Kk / BK;

    auto issue = [&](int kt) {
        int s = kt % STAGES;
        const float* Ag = A + (size_t)row0 * lda + (size_t)kt * BK;
        const float* Bg = B + (size_t)kt * BK * ldb + col0;
        float* Ads = As + s * BM * AP;
        float* Bds = Bs + s * BK * BP;
#pragma unroll
        for (int i = 0; i < 4; i++) {
            int r = arow + i * 32;
            cpa16(Ads + r * AP + acol, Ag + (size_t)r * lda + acol);
        }
#pragma unroll
        for (int i = 0; i < 4; i++) {
            int r = brow + i * 8;
            cpa16(Bds + r * BP + bcol, Bg + (size_t)r * ldb + bcol);
        }
        asm volatile("cp.async.commit_group;");
    };

    issue(0);
    if (nk > 1) issue(1); else asm volatile("cp.async.commit_group;");

    for (int kt = 0; kt < nk; kt++) {
        if (kt < nk - 1) asm volatile("cp.async.wait_group 1;");
        else             asm volatile("cp.async.wait_group 0;");
        __syncthreads();
        if (kt + 2 < nk) issue(kt + 2);

        int s = kt % STAGES;
        const uint32_t* Asl = (const uint32_t*)(As + s * BM * AP);
        const uint32_t* Bsl = (const uint32_t*)(Bs + s * BK * BP);

#pragma unroll
        for (int kk = 0; kk < BK; kk += 8) {
            uint32_t ah[2][4];
#pragma unroll
            for (int mt = 0; mt < 2; mt++) {
                int rb = wm * 32 + mt * 16 + (lane >> 2);
                int cc = kk + (lane & 3);
                ah[mt][0] = Asl[rb * AP + cc];
                ah[mt][1] = Asl[(rb + 8) * AP + cc];
                ah[mt][2] = Asl[rb * AP + cc + 4];
                ah[mt][3] = Asl[(rb + 8) * AP + cc + 4];
            }
#pragma unroll
            for (int nt = 0; nt < 8; nt++) {
                int cb = wn * 64 + nt * 8 + (lane >> 2);
                int r0 = kk + (lane & 3);
                uint32_t bh[2] = {Bsl[r0 * BP + cb], Bsl[(r0 + 4) * BP + cb]};
                mma8(acc[0][nt], ah[0], bh);
                mma8(acc[1][nt], ah[1], bh);
            }
        }
        __syncthreads();
    }

    // epilogue
#pragma unroll
    for (int mt = 0; mt < 2; mt++) {
        int gr = row0 + wm * 32 + mt * 16 + (lane >> 2);
#pragma unroll
        for (int nt = 0; nt < 8; nt++) {
            int gc = col0 + wn * 64 + nt * 8 + (lane & 3) * 2;
            float v00 = acc[mt][nt][0], v01 = acc[mt][nt][1];
            float v10 = acc[mt][nt][2], v11 = acc[mt][nt][3];
            if (EPI == 0 || EPI == 1 || EPI == 3) {
                float b0 = bias[gc], b1 = bias[gc + 1];
                v00 += b0; v01 += b1; v10 += b0; v11 += b1;
            }
            if (EPI == 2) {
                v00 += resid[(size_t)gr * rstride + gc] +
                       resid[(size_t)gr * rstride + DIM + gc];
                v01 += resid[(size_t)gr * rstride + gc + 1] +
                       resid[(size_t)gr * rstride + DIM + gc + 1];
                v10 += resid[(size_t)(gr + 8) * rstride + gc] +
                       resid[(size_t)(gr + 8) * rstride + DIM + gc];
                v11 += resid[(size_t)(gr + 8) * rstride + gc + 1] +
                       resid[(size_t)(gr + 8) * rstride + DIM + gc + 1];
            }
            if (EPI == 0) {
                *(float2*)(C + (size_t)gr * ldc + gc)       = make_float2(v00, v01);
                *(float2*)(C + (size_t)(gr + 8) * ldc + gc) = make_float2(v10, v11);
            } else if (EPI == 1 || EPI == 2) {
                *(float2*)(C + (size_t)gr * ldc + gc) =
                    make_float2(round_tf32(v00), round_tf32(v01));
                *(float2*)(C + (size_t)(gr + 8) * ldc + gc) =
                    make_float2(round_tf32(v10), round_tf32(v11));
            } else if (EPI == 3) {
                // transposed split store: row index = gc (contraction dim of next GEMM)
#pragma unroll
                for (int q = 0; q < 4; q++) {
                    int rr = gr + (q >> 1) * 8;
                    int cc = gc + (q & 1);
                    float v = (q == 0) ? v00 : (q == 1) ? v01 : (q == 2) ? v10 : v11;
                    float hi = round_tf32(v);
                    float lo = round_tf32(v - hi);
                    C[(size_t)cc * ldc + rr]              = hi;
                    C[(size_t)(DIM + cc) * ldc + rr]      = hi;
                    C[(size_t)(2 * DIM + cc) * ldc + rr]  = lo;
                }
            } else if (EPI == 4) {
                // split-3K row store: row index = gr
#pragma unroll
                for (int q = 0; q < 4; q++) {
                    int rr = gr + (q >> 1) * 8;
                    int cc = gc + (q & 1);
                    float v = (q == 0) ? v00 : (q == 1) ? v01 : (q == 2) ? v10 : v11;
                    float hi = round_tf32(v);
                    float lo = round_tf32(v - hi);
                    C[(size_t)rr * ldc + cc]              = hi;
                    C[(size_t)(DIM + rr) * ldc + cc]      = hi;
                    C[(size_t)(2 * DIM + rr) * ldc + cc]  = lo;
                }
            }
        }
    }
}

// ---------------------------------------------------------------------------
// Weight prep kernels (1024x1024 each; grid 4096 x 256)
// ---------------------------------------------------------------------------
__global__ void prep_b3_kernel(const float* __restrict__ W, float* __restrict__ out) {
    int idx = blockIdx.x * 256 + threadIdx.x;
    float w = W[idx];
    float hi = round_tf32(w), lo = round_tf32(w - hi);
    out[idx] = hi;
    out[idx + DIM * DIM] = hi;
    out[idx + 2 * DIM * DIM] = lo;
}
__global__ void prep_a3_kernel(const float* __restrict__ W, float* __restrict__ out) {
    int idx = blockIdx.x * 256 + threadIdx.x;
    int r = idx >> 10, c = idx & 1023;
    float w = W[idx];
    float hi = round_tf32(w), lo = round_tf32(w - hi);
    size_t base = (size_t)r * K3;
    out[base + c] = hi;
    out[base + DIM + c] = lo;
    out[base + 2 * DIM + c] = hi;
}
__global__ void prep_r_kernel(const float* __restrict__ W, float* __restrict__ out) {
    int idx = blockIdx.x * 256 + threadIdx.x;
    out[idx] = round_tf32(W[idx]);
}

// ---------------------------------------------------------------------------
// Block reduction of two values (256 threads)
// ---------------------------------------------------------------------------
__device__ __forceinline__ void blockReduce2(float& a, float& b) {
    __shared__ float sa[8], sb[8];
#pragma unroll
    for (int o = 16; o; o >>= 1) {
        a += __shfl_xor_sync(0xffffffffu, a, o);
        b += __shfl_xor_sync(0xffffffffu, b, o);
    }
    int w = threadIdx.x >> 5, l = threadIdx.x & 31;
    if (l == 0) { sa[w] = a; sb[w] = b; }
    __syncthreads();
    float ta = 0.f, tb = 0.f;
#pragma unroll
    for (int i = 0; i < 8; i++) { ta += sa[i]; tb += sb[i]; }
    a = ta; b = tb;
}

// ---------------------------------------------------------------------------
// LN -> A-side 3K store ([hi | lo | hi])
// ---------------------------------------------------------------------------
__global__ void ln_a3_kernel(const float* __restrict__ x, const float* __restrict__ g,
                             const float* __restrict__ b, float* __restrict__ y3)
{
    size_t bin  = (size_t)blockIdx.x * DIM;
    size_t bout = (size_t)blockIdx.x * K3;
    int t = threadIdx.x;
    float4 v = *(const float4*)(x + bin + t * 4);
    float s  = v.x + v.y + v.z + v.w;
    float ss = v.x * v.x + v.y * v.y + v.z * v.z + v.w * v.w;
    blockReduce2(s, ss);
    float mu  = s * (1.f / DIM);
    float var = ss * (1.f / DIM) - mu * mu;
    float inv = rsqrtf(var + 1e-5f);
    float4 gg = *(const float4*)(g + t * 4);
    float4 bb = *(const float4*)(b + t * 4);
    float o0 = (v.x - mu) * inv * gg.x + bb.x;
    float o1 = (v.y - mu) * inv * gg.y + bb.y;
    float o2 = (v.z - mu) * inv * gg.z + bb.z;
    float o3 = (v.w - mu) * inv * gg.w + bb.w;
    float4 hi = make_float4(round_tf32(o0), round_tf32(o1), round_tf32(o2), round_tf32(o3));
    float4 lo = make_float4(round_tf32(o0 - hi.x), round_tf32(o1 - hi.y),
                            round_tf32(o2 - hi.z), round_tf32(o3 - hi.w));
    *(float4*)(y3 + bout + t * 4)            = hi;
    *(float4*)(y3 + bout + DIM + t * 4)      = lo;
    *(float4*)(y3 + bout + 2 * DIM + t * 4)  = hi;
}

// ---------------------------------------------------------------------------
// logits bias: bias[m] = sum_e bq[e] * k[m,e]  (k = kT3 hi + lo)
// ---------------------------------------------------------------------------
__global__ void bias_kernel(const float* __restrict__ bq, const float* __restrict__ kT3,
                            float* __restrict__ bias)
{
    int m = blockIdx.x, t = threadIdx.x;
    float s = 0.f;
    for (int e = t; e < DIM; e += 256) {
        float k = kT3[(size_t)e * M_OBJ + m] + kT3[(size_t)(2 * DIM + e) * M_OBJ + m];
        s += bq[e] * k;
    }
    float d = 0.f;
    blockReduce2(s, d);
    if (t == 0) bias[m] = s;
}

// ---------------------------------------------------------------------------
// LN -> GELU (-> +resid) ; optional tf32-rounded store
// ---------------------------------------------------------------------------
__device__ __forceinline__ float gelu_exact(float x) {
    return 0.5f * x * (1.f + erff(x * 0.70710678118654752f));
}

template <bool RESID, bool ROUND>
__global__ void ln_gelu_kernel(const float* __restrict__ x, const float* __restrict__ g,
                               const float* __restrict__ b, const float* __restrict__ resid,
                               float* __restrict__ y)
{
    size_t base = (size_t)blockIdx.x * DIM;
    int t = threadIdx.x;
    float4 v = *(const float4*)(x + base + t * 4);
    float s  = v.x + v.y + v.z + v.w;
    float ss = v.x * v.x + v.y * v.y + v.z * v.z + v.w * v.w;
    blockReduce2(s, ss);
    float mu  = s * (1.f / DIM);
    float var = ss * (1.f / DIM) - mu * mu;
    float inv = rsqrtf(var + 1e-5f);
    float4 gg = *(const float4*)(g + t * 4);
    float4 bb = *(const float4*)(b + t * 4);
    float4 o;
    o.x = gelu_exact((v.x - mu) * inv * gg.x + bb.x);
    o.y = gelu_exact((v.y - mu) * inv * gg.y + bb.y);
    o.z = gelu_exact((v.z - mu) * inv * gg.z + bb.z);
    o.w = gelu_exact((v.w - mu) * inv * gg.w + bb.w);
    if (RESID) {
        float4 r = *(const float4*)(resid + base + t * 4);
        o.x += r.x; o.y += r.y; o.z += r.z; o.w += r.w;
    }
    if (ROUND) {
        o.x = round_tf32(o.x); o.y = round_tf32(o.y);
        o.z = round_tf32(o.z); o.w = round_tf32(o.w);
    }
    *(float4*)(y + base + t * 4) = o;
}

// ---------------------------------------------------------------------------
// Softmax over rows of 256 (warp per row), tf32-rounded store
// ---------------------------------------------------------------------------
__global__ void softmax_kernel(float* __restrict__ a)
{
    int row = blockIdx.x * 8 + (threadIdx.x >> 5);
    int l = threadIdx.x & 31;
    float* p = a + (size_t)row * M_OBJ;
    float4 v0 = ((float4*)p)[l];
    float4 v1 = ((float4*)p)[l + 32];
    float m = fmaxf(fmaxf(fmaxf(v0.x, v0.y), fmaxf(v0.z, v0.w)),
                    fmaxf(fmaxf(v1.x, v1.y), fmaxf(v1.z, v1.w)));
#pragma unroll
    for (int o = 16; o; o >>= 1) m = fmaxf(m, __shfl_xor_sync(0xffffffffu, m, o));
    v0.x = __expf(v0.x - m); v0.y = __expf(v0.y - m);
    v0.z = __expf(v0.z - m); v0.w = __expf(v0.w - m);
    v1.x = __expf(v1.x - m); v1.y = __expf(v1.y - m);
    v1.z = __expf(v1.z - m); v1.w = __expf(v1.w - m);
    float s = v0.x + v0.y + v0.z + v0.w + v1.x + v1.y + v1.z + v1.w;
#pragma unroll
    for (int o = 16; o; o >>= 1) s += __shfl_xor_sync(0xffffffffu, s, o);
    float inv = 1.f / s;
    v0.x = round_tf32(v0.x * inv); v0.y = round_tf32(v0.y * inv);
    v0.z = round_tf32(v0.z * inv); v0.w = round_tf32(v0.w * inv);
    v1.x = round_tf32(v1.x * inv); v1.y = round_tf32(v1.y * inv);
    v1.z = round_tf32(v1.z * inv); v1.w = round_tf32(v1.w * inv);
    ((float4*)p)[l] = v0;
    ((float4*)p)[l + 32] = v1;
}

// ---------------------------------------------------------------------------
// BCIM
// ---------------------------------------------------------------------------
__global__ void bcim_norm_kernel(const float* __restrict__ p, float* __restrict__ invn)
{
    int bid = blockIdx.x;
    int b = bid >> 8, hw = bid & 255;
    size_t r0 = ((size_t)b * 512 + hw) * DIM;
    size_t r1 = r0 + (size_t)256 * DIM;
    int t = threadIdx.x;
    float4 a = *(const float4*)(p + r0 + t * 4);
    float4 c = *(const float4*)(p + r1 + t * 4);
    float ss = a.x * a.x + a.y * a.y + a.z * a.z + a.w * a.w +
               c.x * c.x + c.y * c.y + c.z * c.z + c.w * c.w;
    float dummy = 0.f;
    blockReduce2(ss, dummy);
    if (t == 0) invn[bid] = rsqrtf(ss);
}

__global__ void bcim_sim_kernel(const float* __restrict__ p, const float* __restrict__ invn,
                                float* __restrict__ out)
{
    int bid = blockIdx.x;
    int b = bid >> 8, hw = bid & 255;
    int h = hw >> 4, w = hw & 15;
    size_t base = (size_t)b * 512 * DIM;
    int t = threadIdx.x;

    float own[8];
#pragma unroll
    for (int j = 0; j < 8; j++) {
        int e = t + j * 256;
        int row = hw + ((e >> 10) << 8);
        own[j] = p[base + (size_t)row * DIM + (e & 1023)];
    }

    const int DH[8] = {-1, -1, -1, 0, 0, 1, 1, 1};
    const int DW[8] = {-1, 0, 1, -1, 1, -1, 0, 1};
    float dacc[8];
#pragma unroll
    for (int nb = 0; nb < 8; nb++) {
        dacc[nb] = 0.f;
        int h2 = h + DH[nb], w2 = w + DW[nb];
        if ((unsigned)h2 < 16u && (unsigned)w2 < 16u) {
            int hw2 = h2 * 16 + w2;
#pragma unroll
            for (int j = 0; j < 8; j++) {
                int e = t + j * 256;
                int row = hw2 + ((e >> 10) << 8);
                dacc[nb] += own[j] * p[base + (size_t)row * DIM + (e & 1023)];
            }
        }
    }
#pragma unroll
    for (int nb = 0; nb < 8; nb++)
#pragma unroll
        for (int o = 16; o; o >>= 1) dacc[nb] += __shfl_xor_sync(0xffffffffu, dacc[nb], o);

    __shared__ float part[8][8];
    __shared__ float s_sim;
    int wp = t >> 5, l = t & 31;
    if (l == 0) {
#pragma unroll
        for (int nb = 0; nb < 8; nb++) part[wp][nb] = dacc[nb];
    }
    __syncthreads();
    if (t == 0) {
        float inv0 = invn[bid];
        float sim = 1.f;
#pragma unroll
        for (int nb = 0; nb < 8; nb++) {
            int h2 = h + DH[nb], w2 = w + DW[nb];
            if ((unsigned)h2 < 16u && (unsigned)w2 < 16u) {
                float d = 0.f;
                for (int k = 0; k < 8; k++) d += part[k][nb];
                sim += d * inv0 * invn[(b << 8) + h2 * 16 + w2];
            }
        }
        s_sim = sim * (1.f / 9.f);
    }
    __syncthreads();
    float sim = s_sim;
#pragma unroll
    for (int j = 0; j < 8; j++) {
        int e = t + j * 256;
        int row = hw + ((e >> 10) << 8);
        out[base + (size_t)row * DIM + (e & 1023)] = own[j] * sim;
    }
}

// ---------------------------------------------------------------------------
// Launch
// ---------------------------------------------------------------------------
extern "C" void kernel_launch(void* const* d_in, const int* in_sizes, int n_in,
                              void* d_out, int out_size)
{
    const float* p_vec = (const float*)d_in[0];
    const float* obj   = (const float*)d_in[1];
    const float* lnpg  = (const float*)d_in[2];
    const float* lnpb  = (const float*)d_in[3];
    const float* lnog  = (const float*)d_in[4];
    const float* lnob  = (const float*)d_in[5];
    const float* Wq = (const float*)d_in[6],  *bq = (const float*)d_in[7];
    const float* Wk = (const float*)d_in[8],  *bk = (const float*)d_in[9];
    const float* Wv = (const float*)d_in[10], *bv = (const float*)d_in[11];
    const float* W1 = (const float*)d_in[12], *b1 = (const float*)d_in[13];
    const float* l1g = (const float*)d_in[14], *l1b = (const float*)d_in[15];
    const float* W2 = (const float*)d_in[16], *b2 = (const float*)d_in[17];
    const float* l2g = (const float*)d_in[18], *l2b = (const float*)d_in[19];
    float* out = (float*)d_out;

    float *oln3, *Wk3, *Wq3, *Wvr, *W1r, *W2r, *kT3, *Wqk3, *biasb;
    float *pln3, *att, *p1, *G1, *invn;
    cudaGetSymbolAddress((void**)&oln3, g_oln3);
    cudaGetSymbolAddress((void**)&Wk3,  g_Wk3);
    cudaGetSymbolAddress((void**)&Wq3,  g_Wq3);
    cudaGetSymbolAddress((void**)&Wvr,  g_Wvr);
    cudaGetSymbolAddress((void**)&W1r,  g_W1r);
    cudaGetSymbolAddress((void**)&W2r,  g_W2r);
    cudaGetSymbolAddress((void**)&kT3,  g_kT3);
    cudaGetSymbolAddress((void**)&Wqk3, g_Wqk3);
    cudaGetSymbolAddress((void**)&biasb,g_bias);
    cudaGetSymbolAddress((void**)&pln3, g_pln3);
    cudaGetSymbolAddress((void**)&att,  g_att);
    cudaGetSymbolAddress((void**)&p1,   g_p1);
    cudaGetSymbolAddress((void**)&G1,   g_G1);
    cudaGetSymbolAddress((void**)&invn, g_invn);
    float* vbuf = Wqk3 + 0;  // placeholder (not used); v gets its own region below
    // reuse: v lives in the tail of g_Wq3? No — give v its own: reuse g_oln3? o needed.
    // Use g_Wk3's spare? Wk3 is consumed only by k-GEMM which finishes before v-GEMM?
    // Safer: v in a dedicated slice of pln3? pln3 is live until Av. Use g_G1 head?
    // G1 is dead until W1-GEMM (after Av). v needed for Av. So v -> G1 head is UNSAFE?
    // Av reads v while writing p1 (not G1). G1 written only later. SAFE.
    vbuf = G1;  // v occupies first 256*1024 floats of G1; W1-GEMM overwrites later.

    const int SMEM = GEMM_SMEM_BYTES;
    cudaFuncSetAttribute(gemm3<0>, cudaFuncAttributeMaxDynamicSharedMemorySize, SMEM);
    cudaFuncSetAttribute(gemm3<1>, cudaFuncAttributeMaxDynamicSharedMemorySize, SMEM);
    cudaFuncSetAttribute(gemm3<2>, cudaFuncAttributeMaxDynamicSharedMemorySize, SMEM);
    cudaFuncSetAttribute(gemm3<3>, cudaFuncAttributeMaxDynamicSharedMemorySize, SMEM);
    cudaFuncSetAttribute(gemm3<4>, cudaFuncAttributeMaxDynamicSharedMemorySize, SMEM);

    float* G2 = pln3;                              // reuse (dead after Av)
    float* p2 = pln3 + (size_t)R_TOK * DIM;        // reuse

    // ---- prep ----
    prep_b3_kernel<<<4096, 256>>>(Wk, Wk3);
    prep_a3_kernel<<<4096, 256>>>(Wq, Wq3);
    prep_r_kernel<<<4096, 256>>>(Wv, Wvr);
    prep_r_kernel<<<4096, 256>>>(W1, W1r);
    prep_r_kernel<<<4096, 256>>>(W2, W2r);

    // ---- LN ----
    ln_a3_kernel<<<M_OBJ, 256>>>(obj, lnog, lnob, oln3);
    ln_a3_kernel<<<R_TOK, 256>>>(p_vec, lnpg, lnpb, pln3);

    // ---- k^T (split via 3K), bias bk, transposed split store ----
    gemm3<3><<<dim3(DIM / BN, M_OBJ / BM), 256, SMEM>>>(
        oln3, Wk3, bk, nullptr, kT3, M_OBJ, DIM, K3, K3, DIM, M_OBJ, 0);
    // ---- logits bias = bq . k ----
    bias_kernel<<<M_OBJ, 256>>>(bq, kT3, biasb);
    // ---- v = LN(o) @ Wv + bv (plain tf32, rounded store) ----
    gemm3<1><<<dim3(DIM / BN, M_OBJ / BM), 256, SMEM>>>(
        oln3, Wvr, bv, nullptr, vbuf, M_OBJ, DIM, DIM, K3, DIM, DIM, 0);
    // ---- Wqk = Wq @ k^T (split), split-3K row store ----
    gemm3<4><<<dim3(M_OBJ / BN, DIM / BM), 256, SMEM>>>(
        Wq3, kT3, nullptr, nullptr, Wqk3, DIM, M_OBJ, K3, K3, M_OBJ, M_OBJ, 0);
    // ---- logits = pln @ Wqk + bias (split via 3K) ----
    gemm3<0><<<dim3(M_OBJ / BN, R_TOK / BM), 256, SMEM>>>(
        pln3, Wqk3, biasb, nullptr, att, R_TOK, M_OBJ, K3, K3, M_OBJ, M_OBJ, 0);
    // ---- softmax (rounded) ----
    softmax_kernel<<<R_TOK / 8, 256>>>(att);
    // ---- p1 = pln + A @ v (rounded store) ----
    gemm3<2><<<dim3(DIM / BN, R_TOK / BM), 256, SMEM>>>(
        att, vbuf, nullptr, pln3, p1, R_TOK, DIM, M_OBJ, M_OBJ, DIM, DIM, K3);
    // ---- G1 = p1 @ W1 + b1 ; h1 = gelu(LN(G1)) rounded in place ----
    gemm3<0><<<dim3(DIM / BN, R_TOK / BM), 256, SMEM>>>(
        p1, W1r, b1, nullptr, G1, R_TOK, DIM, DIM, DIM, DIM, DIM, 0);
    ln_gelu_kernel<false, true><<<R_TOK, 256>>>(G1, l1g, l1b, nullptr, G1);
    // ---- G2 = h1 @ W2 + b2 ; p2 = p1 + gelu(LN(G2)) ----
    gemm3<0><<<dim3(DIM / BN, R_TOK / BM), 256, SMEM>>>(
        G1, W2r, b2, nullptr, G2, R_TOK, DIM, DIM, DIM, DIM, DIM, 0);
    ln_gelu_kernel<true, false><<<R_TOK, 256>>>(G2, l2g, l2b, p1, p2);
    // ---- BCIM ----
    bcim_norm_kernel<<<64 * 256, 256>>>(p2, invn);
    bcim_sim_kernel<<<64 * 256, 256>>>(p2, invn, out);
}